// round 6
// baseline (speedup 1.0000x reference)
#include <cuda_runtime.h>
#include <cuda_bf16.h>

#define D 128

__global__ __launch_bounds__(256) void arccos_hess_kernel(
    const float* __restrict__ z1,
    const float* __restrict__ z2,
    float* __restrict__ out,
    int B)
{
    int b = blockIdx.x;
    __shared__ float a[D];   // z1 unit vector
    __shared__ float v[D];   // z2 unit vector
    __shared__ float r11[8], r22[8], r12[8];
    __shared__ float s_c, s_i11, s_i12, s_i22, s_rn1, s_rn2;

    int tid = threadIdx.x;

    float x1 = 0.f, x2 = 0.f;
    if (tid < D) {
        x1 = z1[(size_t)b * D + tid];
        x2 = z2[(size_t)b * D + tid];
    }

    // Block reduction of s11, s22, s12
    float p11 = x1 * x1, p22 = x2 * x2, p12 = x1 * x2;
    #pragma unroll
    for (int o = 16; o; o >>= 1) {
        p11 += __shfl_down_sync(0xffffffffu, p11, o);
        p22 += __shfl_down_sync(0xffffffffu, p22, o);
        p12 += __shfl_down_sync(0xffffffffu, p12, o);
    }
    int wid = tid >> 5;
    if ((tid & 31) == 0) { r11[wid] = p11; r22[wid] = p22; r12[wid] = p12; }
    __syncthreads();

    if (tid == 0) {
        float s11 = 0.f, s22 = 0.f, s12 = 0.f;
        #pragma unroll
        for (int w = 0; w < 8; w++) { s11 += r11[w]; s22 += r22[w]; s12 += r12[w]; }
        float rn1 = rsqrtf(s11);
        float rn2 = rsqrtf(s22);
        s_rn1 = rn1;
        s_rn2 = rn2;
        s_c   = s12 * rn1 * rn2;
        s_i11 = rn1 * rn1;
        s_i22 = rn2 * rn2;
        s_i12 = rn1 * rn2;
    }
    __syncthreads();

    if (tid < D) {
        a[tid] = x1 * s_rn1;
        v[tid] = x2 * s_rn2;
    }
    __syncthreads();

    float c   = s_c;
    float i11 = s_i11, i12 = s_i12, i22 = s_i22;
    float c3  = 3.0f * c;

    size_t bdd     = (size_t)b * D * D;
    size_t mstride = (size_t)B * D * D;
    float* o11 = out + bdd;
    float* o12 = out + mstride + bdd;
    float* o22 = out + 2 * mstride + bdd;

    // 128 rows * 32 float4-quads = 4096 slots. Each thread handles 2 slots
    // per iteration (s, s+256), computing 6 float4 results, then issues the
    // 6 STG.128 in one burst for deep DRAM-queue MLP. 8 fixed iterations.
    #pragma unroll
    for (int it = 0; it < 8; it++) {
        int s0 = tid + it * 512;

        float4 h11[2], h12[2], h22[2];
        size_t off[2];

        #pragma unroll
        for (int u = 0; u < 2; u++) {
            int s = s0 + u * 256;
            int i = s >> 5;
            int j = (s & 31) << 2;

            float ai = a[i];
            float vi = v[i];
            float4 aj = *reinterpret_cast<const float4*>(&a[j]);
            float4 vj = *reinterpret_cast<const float4*>(&v[j]);
            const float* paj = &aj.x;
            const float* pvj = &vj.x;

            float* p11o = &h11[u].x;
            float* p12o = &h12[u].x;
            float* p22o = &h22[u].x;

            int d = i - j;   // diagonal when d == k (0..3)

            #pragma unroll
            for (int k = 0; k < 4; k++) {
                float ajk = paj[k], vjk = pvj[k];
                float aa = ai * ajk;
                float vv = vi * vjk;
                float av = ai * vjk;
                float va = vi * ajk;
                float T  = av + va;
                bool  dg = (d == k);
                float ec = dg ? c : 0.f;
                float e1 = dg ? -1.f : 0.f;
                p11o[k] = (ec + T - c3 * aa) * i11;
                p12o[k] = (e1 + aa + vv - c * va) * i12;
                p22o[k] = (ec + T - c3 * vv) * i22;
            }

            off[u] = (size_t)i * D + j;
        }

        // Burst all 6 streaming stores back-to-back.
        __stcs(reinterpret_cast<float4*>(o11 + off[0]), h11[0]);
        __stcs(reinterpret_cast<float4*>(o12 + off[0]), h12[0]);
        __stcs(reinterpret_cast<float4*>(o22 + off[0]), h22[0]);
        __stcs(reinterpret_cast<float4*>(o11 + off[1]), h11[1]);
        __stcs(reinterpret_cast<float4*>(o12 + off[1]), h12[1]);
        __stcs(reinterpret_cast<float4*>(o22 + off[1]), h22[1]);
    }
}

extern "C" void kernel_launch(void* const* d_in, const int* in_sizes, int n_in,
                              void* d_out, int out_size) {
    const float* z1 = (const float*)d_in[0];
    const float* z2 = (const float*)d_in[1];
    float* out = (float*)d_out;
    int B = in_sizes[0] / D;   // 4096
    arccos_hess_kernel<<<B, 256>>>(z1, z2, out, B);
}

// round 7
// speedup vs baseline: 1.2816x; 1.2816x over previous
#include <cuda_runtime.h>
#include <cuda_bf16.h>

#define D 128

__global__ __launch_bounds__(256) void arccos_hess_kernel(
    const float* __restrict__ z1,
    const float* __restrict__ z2,
    float* __restrict__ out,
    int B)
{
    int b0 = blockIdx.x * 2;
    __shared__ float a[2][D];
    __shared__ float v[2][D];
    __shared__ float part[2][3][8];

    int tid  = threadIdx.x;
    int wid  = tid >> 5;
    int lane = tid & 31;

    size_t mstride = (size_t)B * D * D;

    // Load row b0 inputs.
    float x1 = 0.f, x2 = 0.f;
    if (tid < D) {
        x1 = z1[(size_t)b0 * D + tid];
        x2 = z2[(size_t)b0 * D + tid];
    }

    #pragma unroll
    for (int r = 0; r < 2; r++) {
        int b = b0 + r;

        // Prefetch next row's inputs; latency hidden by this row's store loop.
        float nx1 = 0.f, nx2 = 0.f;
        if (r == 0 && tid < D) {
            nx1 = z1[(size_t)(b0 + 1) * D + tid];
            nx2 = z2[(size_t)(b0 + 1) * D + tid];
        }

        // Warp-level reduction of s11, s22, s12.
        float p11 = x1 * x1, p22 = x2 * x2, p12 = x1 * x2;
        #pragma unroll
        for (int o = 16; o; o >>= 1) {
            p11 += __shfl_down_sync(0xffffffffu, p11, o);
            p22 += __shfl_down_sync(0xffffffffu, p22, o);
            p12 += __shfl_down_sync(0xffffffffu, p12, o);
        }
        if (lane == 0) {
            part[r][0][wid] = p11;
            part[r][1][wid] = p22;
            part[r][2][wid] = p12;
        }
        __syncthreads();

        // Every thread finishes the reduction itself (broadcast LDS, no 2nd sync).
        float s11 = 0.f, s22 = 0.f, s12 = 0.f;
        #pragma unroll
        for (int w = 0; w < 8; w++) {
            s11 += part[r][0][w];
            s22 += part[r][1][w];
            s12 += part[r][2][w];
        }
        float rn1 = rsqrtf(s11);
        float rn2 = rsqrtf(s22);
        float c   = s12 * rn1 * rn2;
        float i11 = rn1 * rn1;
        float i22 = rn2 * rn2;
        float i12 = rn1 * rn2;
        float c3  = 3.0f * c;

        if (tid < D) {
            a[r][tid] = x1 * rn1;
            v[r][tid] = x2 * rn2;
        }
        __syncthreads();

        size_t bdd = (size_t)b * D * D;
        float* o11 = out + bdd;
        float* o12 = out + mstride + bdd;
        float* o22 = out + 2 * mstride + bdd;

        // R3 store loop: 4096 quads, stride 256 -> 16 iterations, 3 STG.128 each.
        for (int s = tid; s < D * (D / 4); s += 256) {
            int i = s >> 5;
            int j = (s & 31) << 2;

            float ai = a[r][i];
            float vi = v[r][i];
            float4 aj = *reinterpret_cast<const float4*>(&a[r][j]);
            float4 vj = *reinterpret_cast<const float4*>(&v[r][j]);
            const float* paj = &aj.x;
            const float* pvj = &vj.x;

            float4 h11, h12, h22;
            float* p11o = &h11.x;
            float* p12o = &h12.x;
            float* p22o = &h22.x;

            int d = i - j;   // diagonal when d == k (0..3)

            #pragma unroll
            for (int k = 0; k < 4; k++) {
                float ajk = paj[k], vjk = pvj[k];
                float aa = ai * ajk;
                float vv = vi * vjk;
                float av = ai * vjk;
                float va = vi * ajk;
                float T  = av + va;
                bool  dg = (d == k);
                float ec = dg ? c : 0.f;
                float e1 = dg ? -1.f : 0.f;
                p11o[k] = (ec + T - c3 * aa) * i11;
                p12o[k] = (e1 + aa + vv - c * va) * i12;
                p22o[k] = (ec + T - c3 * vv) * i22;
            }

            size_t off = (size_t)i * D + j;
            __stcs(reinterpret_cast<float4*>(o11 + off), h11);
            __stcs(reinterpret_cast<float4*>(o12 + off), h12);
            __stcs(reinterpret_cast<float4*>(o22 + off), h22);
        }

        x1 = nx1;
        x2 = nx2;
    }
}

extern "C" void kernel_launch(void* const* d_in, const int* in_sizes, int n_in,
                              void* d_out, int out_size) {
    const float* z1 = (const float*)d_in[0];
    const float* z2 = (const float*)d_in[1];
    float* out = (float*)d_out;
    int B = in_sizes[0] / D;   // 4096
    arccos_hess_kernel<<<B / 2, 256>>>(z1, z2, out, B);
}

// round 8
// speedup vs baseline: 1.3569x; 1.0588x over previous
#include <cuda_runtime.h>
#include <cuda_bf16.h>

#define D 128

__global__ __launch_bounds__(256) void arccos_hess_kernel(
    const float* __restrict__ z1,
    const float* __restrict__ z2,
    float* __restrict__ out,
    int B)
{
    // grid = 3*B. m = which matrix (0:H11, 1:H12, 2:H22); b = batch row.
    // Resident CTAs are consecutive b within ONE matrix -> single contiguous
    // DRAM write window chip-wide at any instant.
    int bid = blockIdx.x;
    int m   = bid >= 2 * B ? 2 : (bid >= B ? 1 : 0);
    int b   = bid - m * B;

    __shared__ float a[D];   // z1 unit vector
    __shared__ float v[D];   // z2 unit vector
    __shared__ float part[3][8];

    int tid  = threadIdx.x;
    int wid  = tid >> 5;
    int lane = tid & 31;

    float x1 = 0.f, x2 = 0.f;
    if (tid < D) {
        x1 = z1[(size_t)b * D + tid];
        x2 = z2[(size_t)b * D + tid];
    }

    // Warp reduction of s11, s22, s12.
    float p11 = x1 * x1, p22 = x2 * x2, p12 = x1 * x2;
    #pragma unroll
    for (int o = 16; o; o >>= 1) {
        p11 += __shfl_down_sync(0xffffffffu, p11, o);
        p22 += __shfl_down_sync(0xffffffffu, p22, o);
        p12 += __shfl_down_sync(0xffffffffu, p12, o);
    }
    if (lane == 0) { part[0][wid] = p11; part[1][wid] = p22; part[2][wid] = p12; }
    __syncthreads();

    // Every thread finishes the reduction itself (broadcast LDS).
    float s11 = 0.f, s22 = 0.f, s12 = 0.f;
    #pragma unroll
    for (int w = 0; w < 8; w++) {
        s11 += part[0][w];
        s22 += part[1][w];
        s12 += part[2][w];
    }
    float rn1 = rsqrtf(s11);
    float rn2 = rsqrtf(s22);
    float c   = s12 * rn1 * rn2;
    float c3  = 3.0f * c;

    // Per-matrix scale.
    float scale = (m == 0) ? rn1 * rn1 : (m == 1) ? rn1 * rn2 : rn2 * rn2;

    if (tid < D) {
        a[tid] = x1 * rn1;
        v[tid] = x2 * rn2;
    }
    __syncthreads();

    size_t mstride = (size_t)B * D * D;
    float* o_m = out + (size_t)m * mstride + (size_t)b * D * D;

    // 4096 quads, stride 256 -> 16 iterations, 1 STG.128 each.
    // Matrix branch is uniform per CTA (no divergence).
    if (m == 1) {
        // H12 = (-I + a a^T + v v^T - c * v a^T) * i12
        for (int s = tid; s < D * (D / 4); s += 256) {
            int i = s >> 5;
            int j = (s & 31) << 2;
            float ai = a[i];
            float vi = v[i];
            float4 aj = *reinterpret_cast<const float4*>(&a[j]);
            float4 vj = *reinterpret_cast<const float4*>(&v[j]);
            const float* paj = &aj.x;
            const float* pvj = &vj.x;
            float4 h; float* ph = &h.x;
            int d = i - j;
            #pragma unroll
            for (int k = 0; k < 4; k++) {
                float ajk = paj[k], vjk = pvj[k];
                float e = (d == k) ? -1.f : 0.f;
                ph[k] = (e + ai * ajk + vi * vjk - c * vi * ajk) * scale;
            }
            __stcs(reinterpret_cast<float4*>(o_m + (size_t)i * D + j), h);
        }
    } else {
        // H11 / H22 = (c*I + a v^T + v a^T - 3c * u u^T) * scale,
        // where u = a (m==0) or u = v (m==2).
        for (int s = tid; s < D * (D / 4); s += 256) {
            int i = s >> 5;
            int j = (s & 31) << 2;
            float ai = a[i];
            float vi = v[i];
            float ui = (m == 0) ? ai : vi;
            float4 aj = *reinterpret_cast<const float4*>(&a[j]);
            float4 vj = *reinterpret_cast<const float4*>(&v[j]);
            const float* paj = &aj.x;
            const float* pvj = &vj.x;
            float4 h; float* ph = &h.x;
            int d = i - j;
            #pragma unroll
            for (int k = 0; k < 4; k++) {
                float ajk = paj[k], vjk = pvj[k];
                float ujk = (m == 0) ? ajk : vjk;
                float e = (d == k) ? c : 0.f;
                ph[k] = (e + ai * vjk + vi * ajk - c3 * ui * ujk) * scale;
            }
            __stcs(reinterpret_cast<float4*>(o_m + (size_t)i * D + j), h);
        }
    }
}

extern "C" void kernel_launch(void* const* d_in, const int* in_sizes, int n_in,
                              void* d_out, int out_size) {
    const float* z1 = (const float*)d_in[0];
    const float* z2 = (const float*)d_in[1];
    float* out = (float*)d_out;
    int B = in_sizes[0] / D;   // 4096
    arccos_hess_kernel<<<3 * B, 256>>>(z1, z2, out, B);
}

// round 9
// speedup vs baseline: 1.3607x; 1.0028x over previous
#include <cuda_runtime.h>
#include <cuda_bf16.h>

#define D 128

__global__ __launch_bounds__(256) void arccos_hess_kernel(
    const float* __restrict__ z1,
    const float* __restrict__ z2,
    float* __restrict__ out,
    int B)
{
    // grid = 3*B. m = matrix (0:H11, 1:H12, 2:H22); b = batch row.
    // Resident CTAs cover consecutive b within ONE matrix -> single
    // contiguous DRAM write window chip-wide at any instant.
    int bid = blockIdx.x;
    int m   = bid >= 2 * B ? 2 : (bid >= B ? 1 : 0);
    int b   = bid - m * B;

    __shared__ float a[D];   // z1 unit vector
    __shared__ float v[D];   // z2 unit vector
    __shared__ float part[3][8];

    int tid  = threadIdx.x;
    int wid  = tid >> 5;
    int lane = tid & 31;

    float x1 = 0.f, x2 = 0.f;
    if (tid < D) {
        x1 = z1[(size_t)b * D + tid];
        x2 = z2[(size_t)b * D + tid];
    }

    // Warp reduction of s11, s22, s12.
    float p11 = x1 * x1, p22 = x2 * x2, p12 = x1 * x2;
    #pragma unroll
    for (int o = 16; o; o >>= 1) {
        p11 += __shfl_down_sync(0xffffffffu, p11, o);
        p22 += __shfl_down_sync(0xffffffffu, p22, o);
        p12 += __shfl_down_sync(0xffffffffu, p12, o);
    }
    if (lane == 0) { part[0][wid] = p11; part[1][wid] = p22; part[2][wid] = p12; }
    __syncthreads();

    // Every thread finishes the reduction itself (broadcast LDS).
    float s11 = 0.f, s22 = 0.f, s12 = 0.f;
    #pragma unroll
    for (int w = 0; w < 8; w++) {
        s11 += part[0][w];
        s22 += part[1][w];
        s12 += part[2][w];
    }
    float rn1 = rsqrtf(s11);
    float rn2 = rsqrtf(s22);
    float c   = s12 * rn1 * rn2;
    float c3  = 3.0f * c;
    float scale = (m == 0) ? rn1 * rn1 : (m == 1) ? rn1 * rn2 : rn2 * rn2;

    if (tid < D) {
        a[tid] = x1 * rn1;
        v[tid] = x2 * rn2;
    }
    __syncthreads();

    size_t mstride = (size_t)B * D * D;
    float* o_m = out + (size_t)m * mstride + (size_t)b * D * D;

    // Per-thread: j-quad FIXED across all 16 iterations; i advances by 8.
    int i0 = tid >> 5;          // 0..7
    int j  = (tid & 31) << 2;   // 0,4,...,124 (fixed)

    float4 aj = *reinterpret_cast<const float4*>(&a[j]);
    float4 vj = *reinterpret_cast<const float4*>(&v[j]);
    const float* paj = &aj.x;
    const float* pvj = &vj.x;

    float* row = o_m + (size_t)i0 * D + j;

    if (m == 1) {
        // H12 = (-I + a a^T + v v^T - c * v a^T) * scale
        // Hoist per-j terms: ph[k] = ai*aj[k] + vi*(vj[k] - c*... wait c multiplies va.
        #pragma unroll
        for (int it = 0; it < 16; it++) {
            int i = i0 + it * 8;
            float ai = a[i];
            float vi = v[i];
            float4 h; float* ph = &h.x;
            int d = i - j;
            #pragma unroll
            for (int k = 0; k < 4; k++) {
                float ajk = paj[k], vjk = pvj[k];
                float e = (d == k) ? -1.f : 0.f;
                ph[k] = (e + ai * ajk + vi * vjk - c * vi * ajk) * scale;
            }
            __stcs(reinterpret_cast<float4*>(row), h);
            row += 8 * D;
        }
    } else {
        // H11/H22 = (c*I + a v^T + v a^T - 3c * u u^T) * scale, u = a or v.
        float4 uj;
        uj.x = (m == 0) ? paj[0] : pvj[0];
        uj.y = (m == 0) ? paj[1] : pvj[1];
        uj.z = (m == 0) ? paj[2] : pvj[2];
        uj.w = (m == 0) ? paj[3] : pvj[3];
        const float* puj = &uj.x;

        #pragma unroll
        for (int it = 0; it < 16; it++) {
            int i = i0 + it * 8;
            float ai = a[i];
            float vi = v[i];
            float ui3 = c3 * ((m == 0) ? ai : vi);
            float4 h; float* ph = &h.x;
            int d = i - j;
            #pragma unroll
            for (int k = 0; k < 4; k++) {
                float e = (d == k) ? c : 0.f;
                ph[k] = (e + ai * pvj[k] + vi * paj[k] - ui3 * puj[k]) * scale;
            }
            __stcs(reinterpret_cast<float4*>(row), h);
            row += 8 * D;
        }
    }
}

extern "C" void kernel_launch(void* const* d_in, const int* in_sizes, int n_in,
                              void* d_out, int out_size) {
    const float* z1 = (const float*)d_in[0];
    const float* z2 = (const float*)d_in[1];
    float* out = (float*)d_out;
    int B = in_sizes[0] / D;   // 4096
    arccos_hess_kernel<<<3 * B, 256>>>(z1, z2, out, B);
}